// round 2
// baseline (speedup 1.0000x reference)
#include <cuda_runtime.h>
#include <cuda_bf16.h>

// BoundaryLoss: boundary = (boxsum5(target) > 0) - (boxsum5(target) == 25)
//               loss = mean( BCE(sigmoid(pred), target) * (boundary*4 + 1) )
//
// Fused single-pass kernel: shared-memory target tile with 2-px halo,
// separable 5x5 box sum, stable softplus BCE, hierarchical reduction with
// double-precision block accumulation into a __device__ global.

#define BATCH 32
#define HT 512
#define WD 512
#define TILE 32
#define HALO 2
#define TDIM (TILE + 2 * HALO)   // 36

__device__ double g_accum;

__global__ void zero_accum_kernel() {
    g_accum = 0.0;
}

__global__ __launch_bounds__(1024, 2)
void boundary_loss_kernel(const float* __restrict__ pred,
                          const float* __restrict__ target) {
    __shared__ float t_s[TDIM][TDIM + 1];    // 36x37 target tile w/ halo
    __shared__ float h_s[TDIM][TILE + 1];    // 36x33 horizontal 5-sums
    __shared__ float warp_sums[32];

    const int tx = threadIdx.x;              // 0..31
    const int ty = threadIdx.y;              // 0..31
    const int tid = ty * 32 + tx;            // 0..1023

    const int bx = blockIdx.x;               // tile x (0..15)
    const int by = blockIdx.y;               // tile y (0..15)
    const int b  = blockIdx.z;               // batch  (0..31)

    const int gx0 = bx * TILE - HALO;
    const int gy0 = by * TILE - HALO;
    const float* tgt_img = target + (size_t)b * HT * WD;

    // ---- load target tile with halo (zero padding at image borders) ----
    #pragma unroll
    for (int idx = tid; idx < TDIM * TDIM; idx += 1024) {
        const int r = idx / TDIM;
        const int c = idx - r * TDIM;
        const int gy = gy0 + r;
        const int gx = gx0 + c;
        float v = 0.0f;
        if (gy >= 0 && gy < HT && gx >= 0 && gx < WD)
            v = tgt_img[gy * WD + gx];
        t_s[r][c] = v;
    }
    __syncthreads();

    // ---- horizontal 5-sums: h_s[r][c] = sum_{dx=0..4} t_s[r][c+dx] ----
    #pragma unroll
    for (int idx = tid; idx < TDIM * TILE; idx += 1024) {
        const int r = idx / TILE;
        const int c = idx - r * TILE;
        h_s[r][c] = t_s[r][c] + t_s[r][c + 1] + t_s[r][c + 2]
                  + t_s[r][c + 3] + t_s[r][c + 4];
    }
    __syncthreads();

    // ---- per-pixel: vertical 5-sum, boundary weight, BCE ----
    const float s = h_s[ty][tx] + h_s[ty + 1][tx] + h_s[ty + 2][tx]
                  + h_s[ty + 3][tx] + h_s[ty + 4][tx];
    const float t = t_s[ty + HALO][tx + HALO];

    const float dilated = (s > 0.5f)  ? 1.0f : 0.0f;
    const float eroded  = (s > 24.5f) ? 1.0f : 0.0f;
    const float w = (dilated - eroded) * 4.0f + 1.0f;

    const int gy = by * TILE + ty;
    const int gx = bx * TILE + tx;
    const float x = pred[(size_t)b * HT * WD + gy * WD + gx];

    // BCE(sigmoid(x), t) = softplus(x) - t*x   (clamp at -100 never active
    // for this input range; softplus computed stably)
    const float sp = log1pf(expf(-fabsf(x))) + fmaxf(x, 0.0f);
    const float bce = sp - t * x;

    float v = bce * w;

    // ---- reduction: warp fp32 -> block double -> global atomic ----
    #pragma unroll
    for (int off = 16; off > 0; off >>= 1)
        v += __shfl_xor_sync(0xFFFFFFFFu, v, off);

    const int lane = tx;
    const int wid  = ty;   // warp id == ty since blockDim.x == 32
    if (lane == 0) warp_sums[wid] = v;
    __syncthreads();

    if (wid == 0) {
        double d = (double)warp_sums[lane];
        #pragma unroll
        for (int off = 16; off > 0; off >>= 1)
            d += __shfl_xor_sync(0xFFFFFFFFu, d, off);
        if (lane == 0)
            atomicAdd(&g_accum, d);
    }
}

__global__ void finalize_kernel(float* __restrict__ out) {
    const double n = (double)BATCH * HT * WD;
    out[0] = (float)(g_accum / n);
}

extern "C" void kernel_launch(void* const* d_in, const int* in_sizes, int n_in,
                              void* d_out, int out_size) {
    const float* pred   = (const float*)d_in[0];
    const float* target = (const float*)d_in[1];
    float* out = (float*)d_out;

    zero_accum_kernel<<<1, 1>>>();

    dim3 block(32, 32);
    dim3 grid(WD / TILE, HT / TILE, BATCH);   // 16 x 16 x 32 = 8192 blocks
    boundary_loss_kernel<<<grid, block>>>(pred, target);

    finalize_kernel<<<1, 1>>>(out);
}

// round 3
// speedup vs baseline: 2.7205x; 2.7205x over previous
#include <cuda_runtime.h>
#include <cuda_bf16.h>

// BoundaryLoss fused kernel, v2:
//  - 128x64 tile per 256-thread block, 32 px/thread, float4 everywhere
//  - separable 5x5 box sum: 3x LDS.128 horizontal gather + register vertical slide
//  - per-block partial sums (no atomics, no zeroing kernel)

#define BATCH 32
#define HT 512
#define WD 512
#define TX 128
#define TY 64
#define SROWS (TY + 4)          // 68
#define SCOLS 136               // covers cols [gx0-4, gx0+132), 16B aligned
#define ROWF4 (SCOLS / 4)       // 34
#define GRID_X (WD / TX)        // 4
#define GRID_Y (HT / TY)        // 8
#define NBLK (GRID_X * GRID_Y * BATCH)  // 1024

__device__ double g_partials[NBLK];

__device__ __forceinline__ float bce_w(float x, float t, float s, float& acc) {
    // weight: 5 inside boundary band (0 < boxsum < 25), else 1
    const float w = (s > 0.5f && s < 24.5f) ? 5.0f : 1.0f;
    // BCE(sigmoid(x), t) = softplus(x) - t*x (stable; -100 clamp never active)
    const float sp = log1pf(expf(-fabsf(x))) + fmaxf(x, 0.0f);
    acc += (sp - t * x) * w;
    return w;
}

__global__ __launch_bounds__(256, 4)
void boundary_loss_kernel(const float* __restrict__ pred,
                          const float* __restrict__ target) {
    __shared__ float s_t[SROWS][SCOLS];
    __shared__ float s_warp[8];

    const int tid = threadIdx.x;
    const int bx = blockIdx.x, by = blockIdx.y, b = blockIdx.z;
    const int gx0 = bx * TX, gy0 = by * TY;
    const float* tgt = target + (size_t)b * HT * WD;

    // ---- load target tile (float4, whole-vector OOB predicate: cols are
    //      multiples of 4 and 512 % 4 == 0, so a float4 is fully in or out) ----
    #pragma unroll
    for (int idx = tid; idx < SROWS * ROWF4; idx += 256) {
        const int r  = idx / ROWF4;
        const int c4 = idx - r * ROWF4;
        const int grow = gy0 - 2 + r;
        const int gcol = gx0 - 4 + c4 * 4;
        float4 v = make_float4(0.f, 0.f, 0.f, 0.f);
        if (grow >= 0 && grow < HT && gcol >= 0 && gcol < WD)
            v = *(const float4*)(tgt + (size_t)grow * WD + gcol);
        *(float4*)&s_t[r][c4 * 4] = v;
    }
    __syncthreads();

    // thread -> (column quad, row group)
    const int quad = tid & 31;       // output cols c0..c0+3, c0 = 4*quad
    const int rg   = tid >> 5;       // output rows rg*8 .. rg*8+7
    const int ro0  = rg * 8;
    const int c0   = quad * 4;

    // horizontal 5-sum of smem row sr for this thread's 4 columns.
    // smem float index for output col c spans c+2..c+6 (base shift of 4).
    // Needs floats 4q+2..4q+9 -> float4s q, q+1, q+2 (conflict-free LDS.128).
    // mid (float4 q+1) = floats 4q+4..4q+7 = the raw target values at cols c0..c0+3.
    #define HSUM(sr, h, mid) do {                                   \
        const float4* row_ = (const float4*)&s_t[(sr)][0];          \
        const float4 a_ = row_[quad];                               \
        const float4 b_ = row_[quad + 1];                           \
        const float4 d_ = row_[quad + 2];                           \
        (mid) = b_;                                                 \
        (h).x = a_.z + a_.w + b_.x + b_.y + b_.z;                   \
        (h).y = a_.w + b_.x + b_.y + b_.z + b_.w;                   \
        (h).z = b_.x + b_.y + b_.z + b_.w + d_.x;                   \
        (h).w = b_.y + b_.z + b_.w + d_.x + d_.y;                   \
    } while (0)

    float4 h0, h1, h2, h3, h4, m, cen0, cen1;
    HSUM(ro0 + 0, h0, m);
    HSUM(ro0 + 1, h1, m);
    HSUM(ro0 + 2, h2, m); cen0 = m;   // center for output row ro0
    HSUM(ro0 + 3, h3, m); cen1 = m;   // center for output row ro0+1

    const float* pimg = pred + (size_t)b * HT * WD;
    float acc = 0.0f;

    #pragma unroll
    for (int i = 0; i < 8; i++) {
        const int ro = ro0 + i;
        const float4 p =
            *(const float4*)(pimg + (size_t)(gy0 + ro) * WD + gx0 + c0);

        float4 mnew;
        HSUM(ro + 4, h4, mnew);                 // hs for smem row ro+4
        const float4 tc = (i & 1) ? cen1 : cen0;
        if (i & 1) cen1 = mnew; else cen0 = mnew;  // used again at i+2

        const float sx = h0.x + h1.x + h2.x + h3.x + h4.x;
        const float sy = h0.y + h1.y + h2.y + h3.y + h4.y;
        const float sz = h0.z + h1.z + h2.z + h3.z + h4.z;
        const float sw = h0.w + h1.w + h2.w + h3.w + h4.w;

        bce_w(p.x, tc.x, sx, acc);
        bce_w(p.y, tc.y, sy, acc);
        bce_w(p.z, tc.z, sz, acc);
        bce_w(p.w, tc.w, sw, acc);

        h0 = h1; h1 = h2; h2 = h3; h3 = h4;
    }

    // ---- reduction: warp fp32 shuffle -> smem -> warp0 double -> partial ----
    #pragma unroll
    for (int off = 16; off > 0; off >>= 1)
        acc += __shfl_xor_sync(0xFFFFFFFFu, acc, off);

    const int lane = tid & 31;
    const int wid  = tid >> 5;
    if (lane == 0) s_warp[wid] = acc;
    __syncthreads();

    if (wid == 0 && lane < 8) {
        double d = (double)s_warp[lane];
        #pragma unroll
        for (int off = 4; off > 0; off >>= 1)
            d += __shfl_xor_sync(0x000000FFu, d, off);
        if (lane == 0) {
            const int bid = blockIdx.x + GRID_X * (blockIdx.y + GRID_Y * blockIdx.z);
            g_partials[bid] = d;
        }
    }
}

__global__ __launch_bounds__(256)
void finalize_kernel(float* __restrict__ out) {
    __shared__ double s_warp[8];
    const int tid = threadIdx.x;

    double d = 0.0;
    #pragma unroll
    for (int i = 0; i < NBLK / 256; i++)
        d += g_partials[tid + i * 256];

    #pragma unroll
    for (int off = 16; off > 0; off >>= 1)
        d += __shfl_xor_sync(0xFFFFFFFFu, d, off);

    const int lane = tid & 31, wid = tid >> 5;
    if (lane == 0) s_warp[wid] = d;
    __syncthreads();

    if (tid == 0) {
        double tot = 0.0;
        #pragma unroll
        for (int i = 0; i < 8; i++) tot += s_warp[i];
        out[0] = (float)(tot / ((double)BATCH * HT * WD));
    }
}

extern "C" void kernel_launch(void* const* d_in, const int* in_sizes, int n_in,
                              void* d_out, int out_size) {
    const float* pred   = (const float*)d_in[0];
    const float* target = (const float*)d_in[1];
    float* out = (float*)d_out;

    dim3 grid(GRID_X, GRID_Y, BATCH);   // 4 x 8 x 32 = 1024 blocks
    boundary_loss_kernel<<<grid, 256>>>(pred, target);
    finalize_kernel<<<1, 256>>>(out);
}

// round 4
// speedup vs baseline: 3.5845x; 1.3176x over previous
#include <cuda_runtime.h>
#include <cuda_bf16.h>

// BoundaryLoss fused kernel, v3:
//  - 2x (128x64) tiles per 256-thread block -> 512 blocks = single wave at occ 4
//  - separable 5x5 box sum from smem, float4 LDS.128, register vertical slide
//  - fast-math softplus BCE (2 MUFU ops)
//  - single kernel: last-block finalize via threadfence + arrival counter

#define BATCH 32
#define HT 512
#define WD 512
#define TX 128
#define TY 64
#define SROWS (TY + 4)          // 68
#define SCOLS 136               // covers cols [gx0-4, gx0+132), 16B aligned
#define ROWF4 (SCOLS / 4)       // 34
#define GRID_X (WD / TX)        // 4
#define GRID_Y (HT / TY)        // 8
#define GRID_Z (BATCH / 2)      // 16  (each block does batches bz and bz+16)
#define NBLK (GRID_X * GRID_Y * GRID_Z)  // 512

__device__ double g_partials[NBLK];
__device__ unsigned int g_count;   // zero at load; reset by last block each launch

// horizontal 5-sum of smem row sr for 4 output columns (quad q).
// Output col c uses smem floats c+2..c+6 (tile has a base shift of 4).
// float4s q, q+1, q+2 -> conflict-free LDS.128; mid = raw target at cols c0..c0+3.
#define HSUM(s_t, sr, q, h, mid) do {                               \
    const float4* row_ = (const float4*)&s_t[(sr)][0];              \
    const float4 a_ = row_[(q)];                                    \
    const float4 b_ = row_[(q) + 1];                                \
    const float4 d_ = row_[(q) + 2];                                \
    (mid) = b_;                                                     \
    (h).x = a_.z + a_.w + b_.x + b_.y + b_.z;                       \
    (h).y = a_.w + b_.x + b_.y + b_.z + b_.w;                       \
    (h).z = b_.x + b_.y + b_.z + b_.w + d_.x;                       \
    (h).w = b_.y + b_.z + b_.w + d_.x + d_.y;                       \
} while (0)

__device__ __forceinline__ void bce_w(float x, float t, float s, float& acc) {
    // weight: 5 inside boundary band (0 < boxsum < 25), else 1 (boxsum exact int)
    const float w = (s > 0.5f && s < 24.5f) ? 5.0f : 1.0f;
    // BCE(sigmoid(x), t) = softplus(x) - t*x; stable fast-math softplus.
    const float sp = __logf(1.0f + __expf(-fabsf(x))) + fmaxf(x, 0.0f);
    acc += (sp - t * x) * w;
}

__device__ __forceinline__ float tile_loss(const float* __restrict__ pimg,
                                           const float* __restrict__ tgt,
                                           int gx0, int gy0, int tid,
                                           float (*s_t)[SCOLS]) {
    // ---- load target tile with halo (float4; vector fully in or out) ----
    #pragma unroll
    for (int idx = tid; idx < SROWS * ROWF4; idx += 256) {
        const int r  = idx / ROWF4;
        const int c4 = idx - r * ROWF4;
        const int grow = gy0 - 2 + r;
        const int gcol = gx0 - 4 + c4 * 4;
        float4 v = make_float4(0.f, 0.f, 0.f, 0.f);
        if (grow >= 0 && grow < HT && gcol >= 0 && gcol < WD)
            v = *(const float4*)(tgt + (size_t)grow * WD + gcol);
        *(float4*)&s_t[r][c4 * 4] = v;
    }
    __syncthreads();

    const int quad = tid & 31;       // output cols c0..c0+3, c0 = 4*quad
    const int rg   = tid >> 5;       // output rows rg*8 .. rg*8+7
    const int ro0  = rg * 8;
    const int c0   = quad * 4;

    float4 h0, h1, h2, h3, h4, m, cen0, cen1;
    HSUM(s_t, ro0 + 0, quad, h0, m);
    HSUM(s_t, ro0 + 1, quad, h1, m);
    HSUM(s_t, ro0 + 2, quad, h2, m); cen0 = m;   // center, output row ro0
    HSUM(s_t, ro0 + 3, quad, h3, m); cen1 = m;   // center, output row ro0+1

    float acc = 0.0f;

    #pragma unroll
    for (int i = 0; i < 8; i++) {
        const int ro = ro0 + i;
        const float4 p =
            *(const float4*)(pimg + (size_t)(gy0 + ro) * WD + gx0 + c0);

        float4 mnew;
        HSUM(s_t, ro + 4, quad, h4, mnew);
        const float4 tc = (i & 1) ? cen1 : cen0;
        if (i & 1) cen1 = mnew; else cen0 = mnew;

        const float sx = h0.x + h1.x + h2.x + h3.x + h4.x;
        const float sy = h0.y + h1.y + h2.y + h3.y + h4.y;
        const float sz = h0.z + h1.z + h2.z + h3.z + h4.z;
        const float sw = h0.w + h1.w + h2.w + h3.w + h4.w;

        bce_w(p.x, tc.x, sx, acc);
        bce_w(p.y, tc.y, sy, acc);
        bce_w(p.z, tc.z, sz, acc);
        bce_w(p.w, tc.w, sw, acc);

        h0 = h1; h1 = h2; h2 = h3; h3 = h4;
    }
    return acc;
}

__global__ __launch_bounds__(256, 4)
void boundary_loss_kernel(const float* __restrict__ pred,
                          const float* __restrict__ target,
                          float* __restrict__ out) {
    __shared__ float s_t[SROWS][SCOLS];
    __shared__ float s_warp[8];
    __shared__ unsigned int s_islast;

    const int tid = threadIdx.x;
    const int bx = blockIdx.x, by = blockIdx.y, bz = blockIdx.z;
    const int gx0 = bx * TX, gy0 = by * TY;

    float acc = 0.0f;
    #pragma unroll
    for (int t = 0; t < 2; t++) {
        const int b = bz + t * GRID_Z;
        if (t) __syncthreads();   // protect smem from previous tile's readers
        acc += tile_loss(pred + (size_t)b * HT * WD,
                         target + (size_t)b * HT * WD,
                         gx0, gy0, tid, s_t);
    }

    // ---- block reduction: warp fp32 -> smem -> warp0 double ----
    #pragma unroll
    for (int off = 16; off > 0; off >>= 1)
        acc += __shfl_xor_sync(0xFFFFFFFFu, acc, off);

    const int lane = tid & 31;
    const int wid  = tid >> 5;
    if (lane == 0) s_warp[wid] = acc;
    __syncthreads();

    if (tid == 0) {
        double d = 0.0;
        #pragma unroll
        for (int i = 0; i < 8; i++) d += (double)s_warp[i];
        const int bid = bx + GRID_X * (by + GRID_Y * bz);
        g_partials[bid] = d;
        __threadfence();
        const unsigned int ticket = atomicAdd(&g_count, 1u);
        s_islast = (ticket == NBLK - 1) ? 1u : 0u;
    }
    __syncthreads();

    // ---- last block finalizes ----
    if (s_islast) {
        const volatile double* vp = (const volatile double*)g_partials;
        double d = vp[tid] + vp[tid + 256];

        #pragma unroll
        for (int off = 16; off > 0; off >>= 1)
            d += __shfl_xor_sync(0xFFFFFFFFu, d, off);

        __shared__ double s_dw[8];
        if (lane == 0) s_dw[wid] = d;
        __syncthreads();

        if (tid == 0) {
            double tot = 0.0;
            #pragma unroll
            for (int i = 0; i < 8; i++) tot += s_dw[i];
            out[0] = (float)(tot / ((double)BATCH * HT * WD));
            g_count = 0;   // reset for next graph replay
        }
    }
}

extern "C" void kernel_launch(void* const* d_in, const int* in_sizes, int n_in,
                              void* d_out, int out_size) {
    const float* pred   = (const float*)d_in[0];
    const float* target = (const float*)d_in[1];
    float* out = (float*)d_out;

    dim3 grid(GRID_X, GRID_Y, GRID_Z);   // 4 x 8 x 16 = 512 blocks, single wave
    boundary_loss_kernel<<<grid, 256>>>(pred, target, out);
}

// round 5
// speedup vs baseline: 4.0189x; 1.1212x over previous
#include <cuda_runtime.h>
#include <cuda_bf16.h>

// BoundaryLoss fused kernel, v4: register-streaming, no shared-memory tile.
//  - 128-thread block = full 512-px row width (4 cols/thread, float4)
//  - streams 20 rows (16 output + 4 halo); horizontal 5-sum via 4 warp
//    shuffles + edge-lane float2 patch loads; vertical 5-sum = register
//    running window; target center via 2-deep register delay ring
//  - 1024 blocks, all resident (single wave), zero __syncthreads in hot path
//  - last-block finalize (threadfence + ticket), double accumulation

#define BATCH 32
#define HT 512
#define WD 512
#define ROWS 16                      // output rows per block
#define ITERS (ROWS + 4)             // 20 streamed rows
#define GRID_Y (HT / ROWS)           // 32
#define NBLK (GRID_Y * BATCH)        // 1024

__device__ double g_partials[NBLK];
__device__ unsigned int g_count;     // zero-init; reset by last block each launch

__device__ __forceinline__ void bce_w(float x, float t, float s, float& acc) {
    // weight: 5 inside boundary band (0 < boxsum < 25), else 1 (boxsum exact int)
    const float w = (s > 0.5f && s < 24.5f) ? 5.0f : 1.0f;
    // BCE(sigmoid(x), t) = softplus(x) - t*x; stable fast-math softplus
    const float sp = __logf(1.0f + __expf(-fabsf(x))) + fmaxf(x, 0.0f);
    acc += (sp - t * x) * w;
}

__global__ __launch_bounds__(128, 8)
void boundary_loss_kernel(const float* __restrict__ pred,
                          const float* __restrict__ target,
                          float* __restrict__ out) {
    const int tid  = threadIdx.x;       // 0..127
    const int lane = tid & 31;
    const int wid  = tid >> 5;
    const int c0   = tid * 4;           // this thread's 4 columns

    const int by = blockIdx.x;          // row-chunk (0..31)
    const int b  = blockIdx.y;          // batch     (0..31)

    const float* tgt  = target + (size_t)b * HT * WD;
    const float* pimg = pred   + (size_t)b * HT * WD;
    const int r_base = by * ROWS - 2;   // first streamed row (may be <0)

    const bool has_left  = (lane == 0)  && (c0 > 0);
    const bool has_right = (lane == 31) && (c0 + 4 < WD);

    float4 hring[5];
    float4 cen[2];
    float4 vs = make_float4(0.f, 0.f, 0.f, 0.f);
    float acc = 0.0f;

    #pragma unroll
    for (int j = 0; j < ITERS; j++) {
        const int gr = r_base + j;
        const bool rv = (gr >= 0) && (gr < HT);
        const float* trow = tgt + (size_t)(rv ? gr : 0) * WD;

        // own target quad (cols c0..c0+3)
        float4 t = make_float4(0.f, 0.f, 0.f, 0.f);
        if (rv) t = *(const float4*)(trow + c0);

        // warp-edge halo patches (cols c0-2,c0-1 and c0+4,c0+5)
        float2 pL = make_float2(0.f, 0.f), pR = make_float2(0.f, 0.f);
        if (rv && has_left)  pL = *(const float2*)(trow + c0 - 2);
        if (rv && has_right) pR = *(const float2*)(trow + c0 + 4);

        // neighbors via shuffle; lanes 0/31 override with patches
        float l2 = __shfl_up_sync(0xFFFFFFFFu, t.z, 1);    // col c0-2
        float l1 = __shfl_up_sync(0xFFFFFFFFu, t.w, 1);    // col c0-1
        float r0 = __shfl_down_sync(0xFFFFFFFFu, t.x, 1);  // col c0+4
        float r1 = __shfl_down_sync(0xFFFFFFFFu, t.y, 1);  // col c0+5
        if (lane == 0)  { l2 = pL.x; l1 = pL.y; }
        if (lane == 31) { r0 = pR.x; r1 = pR.y; }

        // horizontal 5-sums for the 4 columns
        const float m3 = t.x + t.y + t.z;
        const float m4 = m3 + t.w;
        float4 hn;
        hn.x = l2 + l1 + m3;
        hn.y = l1 + m4;
        hn.z = m4 + r0;
        hn.w = (m4 - t.x) + r0 + r1;

        // vertical running 5-window (exact: all terms small integers)
        if (j >= 5) {
            const float4 ho = hring[j % 5];
            vs.x -= ho.x; vs.y -= ho.y; vs.z -= ho.z; vs.w -= ho.w;
        }
        vs.x += hn.x; vs.y += hn.y; vs.z += hn.z; vs.w += hn.w;
        hring[j % 5] = hn;

        // center target delay ring (needed 2 iterations later)
        const float4 tc = cen[j & 1];
        cen[j & 1] = t;

        if (j >= 4) {
            const int ro = gr - 2;      // output row, always in [0, HT)
            const float4 p = *(const float4*)(pimg + (size_t)ro * WD + c0);
            bce_w(p.x, tc.x, vs.x, acc);
            bce_w(p.y, tc.y, vs.y, acc);
            bce_w(p.z, tc.z, vs.z, acc);
            bce_w(p.w, tc.w, vs.w, acc);
        }
    }

    // ---- block reduction: warp fp32 -> smem -> double ----
    #pragma unroll
    for (int off = 16; off > 0; off >>= 1)
        acc += __shfl_xor_sync(0xFFFFFFFFu, acc, off);

    __shared__ float s_warp[4];
    __shared__ unsigned int s_islast;
    if (lane == 0) s_warp[wid] = acc;
    __syncthreads();

    if (tid == 0) {
        double d = (double)s_warp[0] + (double)s_warp[1]
                 + (double)s_warp[2] + (double)s_warp[3];
        const int bid = blockIdx.x + GRID_Y * blockIdx.y;
        g_partials[bid] = d;
        __threadfence();
        const unsigned int ticket = atomicAdd(&g_count, 1u);
        s_islast = (ticket == NBLK - 1) ? 1u : 0u;
    }
    __syncthreads();

    // ---- last block finalizes ----
    if (s_islast) {
        const volatile double* vp = (const volatile double*)g_partials;
        double d = 0.0;
        #pragma unroll
        for (int i = 0; i < NBLK / 128; i++)
            d += vp[tid + i * 128];

        #pragma unroll
        for (int off = 16; off > 0; off >>= 1)
            d += __shfl_xor_sync(0xFFFFFFFFu, d, off);

        __shared__ double s_dw[4];
        if (lane == 0) s_dw[wid] = d;
        __syncthreads();

        if (tid == 0) {
            const double tot = s_dw[0] + s_dw[1] + s_dw[2] + s_dw[3];
            out[0] = (float)(tot / ((double)BATCH * HT * WD));
            g_count = 0;    // reset for next graph replay
        }
    }
}

extern "C" void kernel_launch(void* const* d_in, const int* in_sizes, int n_in,
                              void* d_out, int out_size) {
    const float* pred   = (const float*)d_in[0];
    const float* target = (const float*)d_in[1];
    float* out = (float*)d_out;

    dim3 grid(GRID_Y, BATCH);    // 32 x 32 = 1024 blocks, fully resident
    boundary_loss_kernel<<<grid, 128>>>(pred, target, out);
}